// round 1
// baseline (speedup 1.0000x reference)
#include <cuda_runtime.h>
#include <math.h>
#include <stdint.h>

// Problem constants (from reference setup_inputs)
#define CDIM 128
#define HDIM 108
#define WDIM 135
#define HWPX (HDIM * WDIM)
#define WINS 7
#define WIN2 49
#define KPAD 66          // smem row stride (even for float2 align; %32==2 -> <=2-way conflicts)
#define OUTP (2 * WIN2 * WIN2)   // 4802 floats per point

// Transposed feature maps: (H*W, C) channel-contiguous. 2 * 14580 * 128 * 4B = 14.9 MB.
__device__ float g_fmapT[2][HWPX * CDIM];

// ---------------------------------------------------------------------------
// Kernel 1: transpose (C,H,W) -> (H*W, C) for both maps.
// One block per pixel, thread = channel. Writes fully coalesced (512B/block);
// reads hit L2 sectors reused across 8 adjacent-pixel blocks.
// ---------------------------------------------------------------------------
__global__ void transpose_k(const float* __restrict__ fo,
                            const float* __restrict__ fn)
{
    int px = blockIdx.x;
    int c  = threadIdx.x;
    g_fmapT[0][px * CDIM + c] = fo[(size_t)c * HWPX + px];
    g_fmapT[1][px * CDIM + c] = fn[(size_t)c * HWPX + px];
}

// ---------------------------------------------------------------------------
// Kernel 2: one CTA per query point. 256 threads = 8 warps.
//  Phase 0: precompute bilinear (index, weight*valid) for 2 maps x 49 window
//           positions (weights shared across all 128 channels), zero smem pads.
//  Phase 1: sample feat_old -> sA, feat_new -> sB (c-major [C][KPAD]),
//           load anchors -> sC.
//  Phase 2: per-column L2 norms -> inv[] (1/max(||.||,1e-12)).
//  Phase 3: warps 0-3 compute corr_st = sA^T sB, warps 4-7 corr_lt = sC^T sB.
//           Register tile: 4 h-rows x (2 k per lane), A via float2 broadcasts,
//           B via float2 lane loads; norm scaling folded into epilogue.
// ---------------------------------------------------------------------------
__global__ __launch_bounds__(256, 2)
void glu_kernel(const float* __restrict__ queries,
                const float* __restrict__ pred_pos,
                const float* __restrict__ anchors,
                float* __restrict__ out)
{
    extern __shared__ float sm[];
    float* sA   = sm;                       // [CDIM][KPAD] feat_old
    float* sB   = sA + CDIM * KPAD;         // [CDIM][KPAD] feat_new
    float* sC   = sB + CDIM * KPAD;         // [CDIM][KPAD] anchors
    float* inv  = sC + CDIM * KPAD;         // [192]: invA[64], invB[64], invC[64]
    float* wgt  = inv + 192;                // [2*49*4] corner weights
    int*   cidx = (int*)(wgt + 2 * WIN2 * 4); // [2*49*4] corner pixel indices

    const int n = blockIdx.x;
    const int t = threadIdx.x;

    // ---- Phase 0: sampling weights/indices + pad zeroing ----
    if (t < 2 * WIN2) {
        int map = t / WIN2;                 // 0 = old (queries), 1 = new (pred_pos)
        int j   = t % WIN2;
        const float* pt = map ? (pred_pos + 2 * n) : (queries + 2 * n);
        float px = pt[0] * (float)(WDIM - 1);
        float py = pt[1] * (float)(HDIM - 1);
        float ix = px + (float)(j % WINS - 3);
        float iy = py + (float)(j / WINS - 3);
        float x0 = floorf(ix), y0 = floorf(iy);
        float fx = ix - x0,   fy = iy - y0;
        #pragma unroll
        for (int cr = 0; cr < 4; cr++) {
            float xc = x0 + (float)(cr & 1);
            float yc = y0 + (float)(cr >> 1);
            float w  = ((cr & 1) ? fx : 1.0f - fx) * ((cr >> 1) ? fy : 1.0f - fy);
            bool valid = (xc >= 0.0f) && (xc <= (float)(WDIM - 1)) &&
                         (yc >= 0.0f) && (yc <= (float)(HDIM - 1));
            int xi = min(max((int)xc, 0), WDIM - 1);
            int yi = min(max((int)yc, 0), HDIM - 1);
            int slot = (map * WIN2 + j) * 4 + cr;
            wgt[slot]  = valid ? w : 0.0f;
            cidx[slot] = yi * WDIM + xi;
        }
    }
    // zero pad columns k = 49..KPAD-1 of all three tiles (17 cols)
    for (int i = t; i < 3 * CDIM * (KPAD - WIN2); i += 256) {
        int a = i / (CDIM * (KPAD - WIN2));
        int r = (i / (KPAD - WIN2)) % CDIM;
        int k = WIN2 + (i % (KPAD - WIN2));
        sm[a * CDIM * KPAD + r * KPAD + k] = 0.0f;
    }
    if (t < 192) inv[t] = 0.0f;
    __syncthreads();

    // ---- Phase 1: bilinear sampling + anchor load ----
    {
        int cch  = t & 127;
        int half = t >> 7;                  // split 49 positions across two 128-thread halves
        int jbeg = half ? 25 : 0;
        int jend = half ? WIN2 : 25;
        const float* F0 = g_fmapT[0];
        const float* F1 = g_fmapT[1];
        for (int j = jbeg; j < jend; j++) {
            const float* w0 = wgt + j * 4;
            const int*   i0 = cidx + j * 4;
            float v = w0[0] * F0[i0[0] * CDIM + cch]
                    + w0[1] * F0[i0[1] * CDIM + cch]
                    + w0[2] * F0[i0[2] * CDIM + cch]
                    + w0[3] * F0[i0[3] * CDIM + cch];
            sA[cch * KPAD + j] = v;
            const float* w1 = wgt + (WIN2 + j) * 4;
            const int*   i1 = cidx + (WIN2 + j) * 4;
            float u = w1[0] * F1[i1[0] * CDIM + cch]
                    + w1[1] * F1[i1[1] * CDIM + cch]
                    + w1[2] * F1[i1[2] * CDIM + cch]
                    + w1[3] * F1[i1[3] * CDIM + cch];
            sB[cch * KPAD + j] = u;
        }
    }
    {
        const float4* anc4 = reinterpret_cast<const float4*>(
            anchors + (size_t)n * (CDIM * WIN2));
        for (int i = t; i < (CDIM * WIN2) / 4; i += 256) {
            float4 v = anc4[i];
            int e = i * 4;
            const float* vf = (const float*)&v;
            #pragma unroll
            for (int q = 0; q < 4; q++) {
                int ee = e + q;
                sC[(ee / WIN2) * KPAD + (ee % WIN2)] = vf[q];
            }
        }
    }
    __syncthreads();

    // ---- Phase 2: column norms -> inverse scales ----
    {
        int w = t >> 5, l = t & 31;
        for (int j = w; j < WIN2; j += 8) {
            float s0 = 0.f, s1 = 0.f, s2 = 0.f;
            #pragma unroll
            for (int cc = l; cc < CDIM; cc += 32) {
                float x = sA[cc * KPAD + j]; s0 += x * x;
                float y = sB[cc * KPAD + j]; s1 += y * y;
                float z = sC[cc * KPAD + j]; s2 += z * z;
            }
            #pragma unroll
            for (int o = 16; o; o >>= 1) {
                s0 += __shfl_xor_sync(0xFFFFFFFFu, s0, o);
                s1 += __shfl_xor_sync(0xFFFFFFFFu, s1, o);
                s2 += __shfl_xor_sync(0xFFFFFFFFu, s2, o);
            }
            if (l == 0) {
                inv[j]       = 1.0f / fmaxf(sqrtf(s0), 1e-12f);
                inv[64 + j]  = 1.0f / fmaxf(sqrtf(s1), 1e-12f);
                inv[128 + j] = 1.0f / fmaxf(sqrtf(s2), 1e-12f);
            }
        }
    }
    __syncthreads();

    // ---- Phase 3: correlations ----
    {
        int w  = t >> 5;
        int l  = t & 31;
        int corrSel = w >> 2;               // 0: short-term (sA), 1: long-term (sC)
        int wq = w & 3;
        const float* P    = corrSel ? sC : sA;
        const float* pinv = corrSel ? (inv + 128) : inv;
        int kk = 2 * l;                     // this lane's k pair (covers k 0..63; pads are 0)
        float ib0 = inv[64 + kk];
        float ib1 = inv[64 + kk + 1];
        float* op = out + (size_t)n * OUTP + corrSel * (WIN2 * WIN2);

        for (int g = wq; g < 13; g += 4) {  // 13 groups of 4 h-rows (last ragged into pads)
            int h0 = g * 4;
            float a00 = 0.f, a01 = 0.f, a10 = 0.f, a11 = 0.f;
            float a20 = 0.f, a21 = 0.f, a30 = 0.f, a31 = 0.f;
            #pragma unroll 4
            for (int cc = 0; cc < CDIM; cc++) {
                const float* rp = P  + cc * KPAD;
                const float* bp = sB + cc * KPAD;
                float2 ah0 = *(const float2*)(rp + h0);      // broadcast (8B)
                float2 ah2 = *(const float2*)(rp + h0 + 2);  // broadcast (8B)
                float2 b   = *(const float2*)(bp + kk);      // lane-strided, conflict-free
                a00 += ah0.x * b.x; a01 += ah0.x * b.y;
                a10 += ah0.y * b.x; a11 += ah0.y * b.y;
                a20 += ah2.x * b.x; a21 += ah2.x * b.y;
                a30 += ah2.y * b.x; a31 += ah2.y * b.y;
            }
            float r0[4] = {a00, a10, a20, a30};
            float r1[4] = {a01, a11, a21, a31};
            #pragma unroll
            for (int i = 0; i < 4; i++) {
                int h = h0 + i;
                if (h < WIN2) {
                    float ia = pinv[h];
                    if (kk < WIN2)     op[h * WIN2 + kk]     = r0[i] * (ia * ib0);
                    if (kk + 1 < WIN2) op[h * WIN2 + kk + 1] = r1[i] * (ia * ib1);
                }
            }
        }
    }
}

// ---------------------------------------------------------------------------
// Launch
// ---------------------------------------------------------------------------
extern "C" void kernel_launch(void* const* d_in, const int* in_sizes, int n_in,
                              void* d_out, int out_size)
{
    const float* fmap_old = (const float*)d_in[0];
    const float* fmap_new = (const float*)d_in[1];
    const float* queries  = (const float*)d_in[2];
    const float* pred_pos = (const float*)d_in[3];
    const float* anchors  = (const float*)d_in[4];
    float* out = (float*)d_out;

    const int N = in_sizes[2] / 2;

    const int SMEM_BYTES = (3 * CDIM * KPAD + 192 + 2 * WIN2 * 4) * (int)sizeof(float)
                         + 2 * WIN2 * 4 * (int)sizeof(int);

    cudaFuncSetAttribute(glu_kernel,
                         cudaFuncAttributeMaxDynamicSharedMemorySize, SMEM_BYTES);

    transpose_k<<<HWPX, CDIM>>>(fmap_old, fmap_new);
    glu_kernel<<<N, 256, SMEM_BYTES>>>(queries, pred_pos, anchors, out);
}

// round 4
// speedup vs baseline: 1.2483x; 1.2483x over previous
#include <cuda_runtime.h>
#include <cuda_bf16.h>
#include <math.h>
#include <stdint.h>

// ---------------- problem constants ----------------
#define CDIM 128
#define HDIM 108
#define WDIM 135
#define HWPX (HDIM * WDIM)
#define WINS 7
#define WIN2 49
#define OUTP (2 * WIN2 * WIN2)          // 4802 floats / point

// ---------------- smem layout ----------------
// Row-major bf16 tiles, stride KS=136 elements (272 B -> conflict-free ldmatrix).
// A: 112 rows (feat_old 0-48, anchors 49-97, 98-111 pad/garbage)
// B: 56 rows  (feat_new 0-48, 49-55 pad/garbage)
#define KS 136
#define A_ROWS 112
#define B_ROWS 56
#define A_BYTES (A_ROWS * KS * 2)       // 30464
#define B_BYTES (B_ROWS * KS * 2)       // 15232
#define SM_AHI 0
#define SM_ALO (SM_AHI + A_BYTES)
#define SM_BHI (SM_ALO + A_BYTES)
#define SM_BLO (SM_BHI + B_BYTES)
#define SM_INV (SM_BLO + B_BYTES)       // 160 floats: invA[0..97], invB at [98..146]
#define SM_WGT (SM_INV + 640)           // 2*49*4 floats
#define SM_IDX (SM_WGT + 1568)          // 2*49*4 ints
#define SMEM_TOTAL (SM_IDX + 1568)      // 95168 B -> 2 CTAs/SM

// Transposed fmaps: (H*W, C) channel-contiguous (L2-resident, 14.9 MB)
__device__ float g_fmapT[2][HWPX * CDIM];

// ---------------- helpers ----------------
__device__ __forceinline__ uint32_t smem_u32(const void* p) {
    uint32_t a;
    asm("{ .reg .u64 t; cvta.to.shared.u64 t, %1; cvt.u32.u64 %0, t; }"
        : "=r"(a) : "l"(p));
    return a;
}

__device__ __forceinline__ void ldsm4(uint32_t* r, uint32_t addr) {
    asm volatile("ldmatrix.sync.aligned.m8n8.x4.shared.b16 {%0,%1,%2,%3}, [%4];"
                 : "=r"(r[0]), "=r"(r[1]), "=r"(r[2]), "=r"(r[3]) : "r"(addr));
}
__device__ __forceinline__ void ldsm2(uint32_t* r, uint32_t addr) {
    asm volatile("ldmatrix.sync.aligned.m8n8.x2.shared.b16 {%0,%1}, [%2];"
                 : "=r"(r[0]), "=r"(r[1]) : "r"(addr));
}
__device__ __forceinline__ void mma16816(float* c, const uint32_t* a, const uint32_t* b) {
    asm volatile(
        "mma.sync.aligned.m16n8k16.row.col.f32.bf16.bf16.f32 "
        "{%0,%1,%2,%3}, {%4,%5,%6,%7}, {%8,%9}, {%0,%1,%2,%3};"
        : "+f"(c[0]), "+f"(c[1]), "+f"(c[2]), "+f"(c[3])
        : "r"(a[0]), "r"(a[1]), "r"(a[2]), "r"(a[3]), "r"(b[0]), "r"(b[1]));
}

// ---------------------------------------------------------------------------
// transpose (C,H,W) -> (H*W, C)
// ---------------------------------------------------------------------------
__global__ void transpose_k(const float* __restrict__ fo,
                            const float* __restrict__ fn)
{
    int px = blockIdx.x;
    int c  = threadIdx.x;
    g_fmapT[0][px * CDIM + c] = fo[(size_t)c * HWPX + px];
    g_fmapT[1][px * CDIM + c] = fn[(size_t)c * HWPX + px];
}

// ---------------------------------------------------------------------------
// main kernel: one CTA per point, 256 threads
// ---------------------------------------------------------------------------
__global__ __launch_bounds__(256, 2)
void glu_hmma_kernel(const float* __restrict__ queries,
                     const float* __restrict__ pred_pos,
                     const float* __restrict__ anchors,
                     float* __restrict__ out)
{
    extern __shared__ char smc[];
    const uint32_t sbase = smem_u32(smc);
    const int n = blockIdx.x;
    const int t = threadIdx.x;
    const int w = t >> 5;
    const int l = t & 31;

    float* inv  = (float*)(smc + SM_INV);
    float* wgt  = (float*)(smc + SM_WGT);
    int*   cidx = (int*)(smc + SM_IDX);

    // ---- Phase 0: bilinear weights/indices (shared across channels) ----
    if (t < 2 * WIN2) {
        int map = t / WIN2;
        int j   = t % WIN2;
        const float* pt = map ? (pred_pos + 2 * n) : (queries + 2 * n);
        float px = pt[0] * (float)(WDIM - 1);
        float py = pt[1] * (float)(HDIM - 1);
        float ix = px + (float)(j % WINS - 3);
        float iy = py + (float)(j / WINS - 3);
        float x0 = floorf(ix), y0 = floorf(iy);
        float fx = ix - x0,   fy = iy - y0;
        #pragma unroll
        for (int cr = 0; cr < 4; cr++) {
            float xc = x0 + (float)(cr & 1);
            float yc = y0 + (float)(cr >> 1);
            float wv = ((cr & 1) ? fx : 1.0f - fx) * ((cr >> 1) ? fy : 1.0f - fy);
            bool valid = (xc >= 0.0f) && (xc <= (float)(WDIM - 1)) &&
                         (yc >= 0.0f) && (yc <= (float)(HDIM - 1));
            int xi = min(max((int)xc, 0), WDIM - 1);
            int yi = min(max((int)yc, 0), HDIM - 1);
            int slot = t * 4 + cr;
            wgt[slot]  = valid ? wv : 0.0f;
            cidx[slot] = yi * WDIM + xi;
        }
    }
    __syncthreads();

    // ---- Phase 1a: bilinear sample -> bf16 hi/lo tiles (A rows 0-48, B rows 0-48)
    {
        int cch  = t & 127;
        int half = t >> 7;
        int jbeg = half ? 25 : 0;
        int jend = half ? WIN2 : 25;
        const float* F0 = g_fmapT[0];
        const float* F1 = g_fmapT[1];
        for (int j = jbeg; j < jend; j++) {
            const float* w0 = wgt + j * 4;
            const int*   i0 = cidx + j * 4;
            float v = w0[0] * F0[i0[0] * CDIM + cch]
                    + w0[1] * F0[i0[1] * CDIM + cch]
                    + w0[2] * F0[i0[2] * CDIM + cch]
                    + w0[3] * F0[i0[3] * CDIM + cch];
            __nv_bfloat16 vh = __float2bfloat16(v);
            __nv_bfloat16 vl = __float2bfloat16(v - __bfloat162float(vh));
            uint32_t oa = (uint32_t)(j * KS + cch) * 2u;
            *(__nv_bfloat16*)(smc + SM_AHI + oa) = vh;
            *(__nv_bfloat16*)(smc + SM_ALO + oa) = vl;

            const float* w1 = wgt + (WIN2 + j) * 4;
            const int*   i1 = cidx + (WIN2 + j) * 4;
            float u = w1[0] * F1[i1[0] * CDIM + cch]
                    + w1[1] * F1[i1[1] * CDIM + cch]
                    + w1[2] * F1[i1[2] * CDIM + cch]
                    + w1[3] * F1[i1[3] * CDIM + cch];
            __nv_bfloat16 uh = __float2bfloat16(u);
            __nv_bfloat16 ul = __float2bfloat16(u - __bfloat162float(uh));
            *(__nv_bfloat16*)(smc + SM_BHI + oa) = uh;
            *(__nv_bfloat16*)(smc + SM_BLO + oa) = ul;
        }
    }
    // ---- Phase 1b: anchors -> A rows 49..97 ----
    {
        const float4* anc4 = (const float4*)(anchors + (size_t)n * (CDIM * WIN2));
        for (int i = t; i < (CDIM * WIN2) / 4; i += 256) {
            float4 v = anc4[i];
            const float* vf = (const float*)&v;
            int e = i * 4;
            #pragma unroll
            for (int q = 0; q < 4; q++) {
                int ee = e + q;
                int c = ee / WIN2;
                int j = ee - c * WIN2;
                float x = vf[q];
                __nv_bfloat16 xh = __float2bfloat16(x);
                __nv_bfloat16 xl = __float2bfloat16(x - __bfloat162float(xh));
                uint32_t oa = (uint32_t)((49 + j) * KS + c) * 2u;
                *(__nv_bfloat16*)(smc + SM_AHI + oa) = xh;
                *(__nv_bfloat16*)(smc + SM_ALO + oa) = xl;
            }
        }
    }
    __syncthreads();

    // ---- Phase 2: per-row L2 norms (hi+lo reconstruction) ----
    for (int r = w; r < 147; r += 8) {
        float s = 0.0f;
        int isA = (r < 98);
        int row = isA ? r : (r - 98);
        int hb  = isA ? SM_AHI : SM_BHI;
        int lb  = isA ? SM_ALO : SM_BLO;
        #pragma unroll
        for (int i = 0; i < 4; i++) {
            int k = l + 32 * i;
            uint32_t o = (uint32_t)(row * KS + k) * 2u;
            float v = __bfloat162float(*(const __nv_bfloat16*)(smc + hb + o))
                    + __bfloat162float(*(const __nv_bfloat16*)(smc + lb + o));
            s += v * v;
        }
        #pragma unroll
        for (int o = 16; o; o >>= 1) s += __shfl_xor_sync(0xFFFFFFFFu, s, o);
        if (l == 0) inv[r] = 1.0f / fmaxf(sqrtf(s), 1e-12f);
    }
    __syncthreads();

    // ---- Phase 3: HMMA correlations, warps 0-6, m-tile = 16w ----
    if (w < 7) {
        const int m0 = w * 16;
        const int lrow = l & 7, lq = l >> 3;
        // A fragment ldmatrix.x4 lane addressing (quadrants: +8 rows / +8 cols)
        uint32_t aoff = (uint32_t)((m0 + lrow + ((lq & 1) << 3)) * KS
                                   + ((lq >> 1) << 3)) * 2u;
        uint32_t aAhi = sbase + SM_AHI + aoff;
        uint32_t aAlo = sbase + SM_ALO + aoff;

        uint32_t ahi[8][4], alo[8][4];
        #pragma unroll
        for (int k8 = 0; k8 < 8; k8++) {
            ldsm4(ahi[k8], aAhi + 32u * k8);   // 16 k-elems = 32 B step
            ldsm4(alo[k8], aAlo + 32u * k8);
        }

        // B fragment ldmatrix.x2 lane addressing (lanes 0-15 meaningful)
        const int li = l & 15;
        uint32_t boff = (uint32_t)(((li & 7) * KS) + ((li >> 3) << 3)) * 2u;

        const int r0 = m0 + (l >> 2);
        const int r1 = r0 + 8;
        const int kc = (l & 3) << 1;           // col offset within n-tile

        float ia0 = 0.f, ia1 = 0.f;
        int sel0 = 0, h0 = 0, sel1 = 0, h1 = 0;
        if (r0 < 98) { ia0 = inv[r0]; sel0 = (r0 >= 49); h0 = r0 - sel0 * 49; }
        if (r1 < 98) { ia1 = inv[r1]; sel1 = (r1 >= 49); h1 = r1 - sel1 * 49; }
        float* outp = out + (size_t)n * OUTP;

        #pragma unroll
        for (int nt = 0; nt < 7; nt++) {
            const int n0 = nt * 8;
            uint32_t bh_a = sbase + SM_BHI + boff + (uint32_t)(n0 * KS) * 2u;
            uint32_t bl_a = sbase + SM_BLO + boff + (uint32_t)(n0 * KS) * 2u;
            float acc[4] = {0.f, 0.f, 0.f, 0.f};
            #pragma unroll
            for (int k8 = 0; k8 < 8; k8++) {
                uint32_t bh[2], bl[2];
                ldsm2(bh, bh_a + 32u * k8);
                ldsm2(bl, bl_a + 32u * k8);
                mma16816(acc, ahi[k8], bh);    // hi*hi
                mma16816(acc, ahi[k8], bl);    // hi*lo
                mma16816(acc, alo[k8], bh);    // lo*hi
            }
            const int k0 = n0 + kc;
            const int k1 = k0 + 1;
            float ib0 = inv[98 + k0];          // reads within padded inv[160]
            float ib1 = inv[98 + k1];
            if (r0 < 98) {
                float* op = outp + sel0 * (WIN2 * WIN2) + h0 * WIN2;
                if (k0 < WIN2) op[k0] = acc[0] * ia0 * ib0;
                if (k1 < WIN2) op[k1] = acc[1] * ia0 * ib1;
            }
            if (r1 < 98) {
                float* op = outp + sel1 * (WIN2 * WIN2) + h1 * WIN2;
                if (k0 < WIN2) op[k0] = acc[2] * ia1 * ib0;
                if (k1 < WIN2) op[k1] = acc[3] * ia1 * ib1;
            }
        }
    }
}

// ---------------------------------------------------------------------------
extern "C" void kernel_launch(void* const* d_in, const int* in_sizes, int n_in,
                              void* d_out, int out_size)
{
    const float* fmap_old = (const float*)d_in[0];
    const float* fmap_new = (const float*)d_in[1];
    const float* queries  = (const float*)d_in[2];
    const float* pred_pos = (const float*)d_in[3];
    const float* anchors  = (const float*)d_in[4];
    float* out = (float*)d_out;

    const int N = in_sizes[2] / 2;

    cudaFuncSetAttribute(glu_hmma_kernel,
                         cudaFuncAttributeMaxDynamicSharedMemorySize, SMEM_TOTAL);

    transpose_k<<<HWPX, CDIM>>>(fmap_old, fmap_new);
    glu_hmma_kernel<<<N, 256, SMEM_TOTAL>>>(queries, pred_pos, anchors, out);
}

// round 5
// speedup vs baseline: 2.1430x; 1.7167x over previous
#include <cuda_runtime.h>
#include <cuda_bf16.h>
#include <math.h>
#include <stdint.h>

// ---------------- problem constants ----------------
#define CDIM 128
#define HDIM 108
#define WDIM 135
#define HWPX (HDIM * WDIM)
#define WINS 7
#define WIN2 49
#define OUTP (2 * WIN2 * WIN2)          // 4802 floats / point

// ---------------- smem layout ----------------
#define KS 136                           // bf16 row stride (272B, ldmatrix conflict-free)
#define A_ROWS 112
#define B_ROWS 56
#define A_BYTES (A_ROWS * KS * 2)       // 30464
#define B_BYTES (B_ROWS * KS * 2)       // 15232
#define SM_AHI 0
#define SM_ALO (SM_AHI + A_BYTES)
#define SM_BHI (SM_ALO + A_BYTES)       // also anchor fp32 staging (27136B <= 30464B)
#define SM_BLO (SM_BHI + B_BYTES)
#define SM_INV (SM_BLO + B_BYTES)       // 160 floats
#define SM_WGT (SM_INV + 640)           // 98*4 floats
#define SM_IDX (SM_WGT + 1568)          // 98*4 ints
#define SMEM_TOTAL (SM_IDX + 1568)      // 95168 B -> 2 CTAs/SM
#define STG_S 53                         // anchor staging stride (odd -> conflict-free)

// Transposed fmaps: (H*W, C) channel-contiguous (L2-resident, 14.9 MB)
__device__ float g_fmapT[2][HWPX * CDIM];

// ---------------- helpers ----------------
__device__ __forceinline__ uint32_t smem_u32(const void* p) {
    uint32_t a;
    asm("{ .reg .u64 t; cvta.to.shared.u64 t, %1; cvt.u32.u64 %0, t; }"
        : "=r"(a) : "l"(p));
    return a;
}
__device__ __forceinline__ void ldsm4(uint32_t* r, uint32_t addr) {
    asm volatile("ldmatrix.sync.aligned.m8n8.x4.shared.b16 {%0,%1,%2,%3}, [%4];"
                 : "=r"(r[0]), "=r"(r[1]), "=r"(r[2]), "=r"(r[3]) : "r"(addr));
}
__device__ __forceinline__ void ldsm2(uint32_t* r, uint32_t addr) {
    asm volatile("ldmatrix.sync.aligned.m8n8.x2.shared.b16 {%0,%1}, [%2];"
                 : "=r"(r[0]), "=r"(r[1]) : "r"(addr));
}
__device__ __forceinline__ void mma16816(float* c, const uint32_t* a, const uint32_t* b) {
    asm volatile(
        "mma.sync.aligned.m16n8k16.row.col.f32.bf16.bf16.f32 "
        "{%0,%1,%2,%3}, {%4,%5,%6,%7}, {%8,%9}, {%0,%1,%2,%3};"
        : "+f"(c[0]), "+f"(c[1]), "+f"(c[2]), "+f"(c[3])
        : "r"(a[0]), "r"(a[1]), "r"(a[2]), "r"(a[3]), "r"(b[0]), "r"(b[1]));
}

// ---------------------------------------------------------------------------
__global__ void transpose_k(const float* __restrict__ fo,
                            const float* __restrict__ fn)
{
    int px = blockIdx.x;
    int c  = threadIdx.x;
    g_fmapT[0][px * CDIM + c] = fo[(size_t)c * HWPX + px];
    g_fmapT[1][px * CDIM + c] = fn[(size_t)c * HWPX + px];
}

// ---------------------------------------------------------------------------
// main kernel: one CTA per point, 256 threads
// ---------------------------------------------------------------------------
__global__ __launch_bounds__(256, 2)
void glu_hmma_kernel(const float* __restrict__ queries,
                     const float* __restrict__ pred_pos,
                     const float* __restrict__ anchors,
                     float* __restrict__ out)
{
    extern __shared__ char smc[];
    const uint32_t sbase = smem_u32(smc);
    const int n = blockIdx.x;
    const int t = threadIdx.x;
    const int w = t >> 5;
    const int l = t & 31;

    float* inv  = (float*)(smc + SM_INV);
    float* wgt  = (float*)(smc + SM_WGT);
    int*   cidx = (int*)(smc + SM_IDX);
    float* stg  = (float*)(smc + SM_BHI);    // anchor fp32 staging [128][STG_S]

    // ---- Phase 0a: anchor fp32 staged coalesced into smem ----
    {
        const float* anc = anchors + (size_t)n * (CDIM * WIN2);
        #pragma unroll
        for (int q = 0; q < 25; q++) {
            int e = t + 256 * q;
            if (e < CDIM * WIN2) {
                int c = e / WIN2;
                int j = e - c * WIN2;
                stg[c * STG_S + j] = anc[e];
            }
        }
    }
    // ---- Phase 0b: bilinear weights/indices (one thread per (map,j)) ----
    if (t < 2 * WIN2) {
        int map = t / WIN2;
        int j   = t % WIN2;
        const float* pt = map ? (pred_pos + 2 * n) : (queries + 2 * n);
        float px = pt[0] * (float)(WDIM - 1);
        float py = pt[1] * (float)(HDIM - 1);
        float ix = px + (float)(j % WINS - 3);
        float iy = py + (float)(j / WINS - 3);
        float x0 = floorf(ix), y0 = floorf(iy);
        float fx = ix - x0,   fy = iy - y0;
        #pragma unroll
        for (int cr = 0; cr < 4; cr++) {
            float xc = x0 + (float)(cr & 1);
            float yc = y0 + (float)(cr >> 1);
            float wv = ((cr & 1) ? fx : 1.0f - fx) * ((cr >> 1) ? fy : 1.0f - fy);
            bool valid = (xc >= 0.0f) && (xc <= (float)(WDIM - 1)) &&
                         (yc >= 0.0f) && (yc <= (float)(HDIM - 1));
            int xi = min(max((int)xc, 0), WDIM - 1);
            int yi = min(max((int)yc, 0), HDIM - 1);
            wgt[t * 4 + cr]  = valid ? wv : 0.0f;
            cidx[t * 4 + cr] = yi * WDIM + xi;
        }
    }
    __syncthreads();

    // ---- Phase 1: anchor transpose/convert -> A rows 49..97 + row norms ----
    #pragma unroll
    for (int m = 0; m < 7; m++) {
        int rr = w + 8 * m;                  // 0..55
        if (rr < WIN2) {
            int row = 49 + rr;
            float s = 0.0f;
            #pragma unroll
            for (int q = 0; q < 4; q++) {
                int c = l + 32 * q;
                float x = stg[c * STG_S + rr];      // banks 53*l mod 32: all distinct
                __nv_bfloat16 xh = __float2bfloat16(x);
                __nv_bfloat16 xl = __float2bfloat16(x - __bfloat162float(xh));
                uint32_t o = (uint32_t)(row * KS + c) * 2u;
                *(__nv_bfloat16*)(smc + SM_AHI + o) = xh;    // contiguous 2B STS
                *(__nv_bfloat16*)(smc + SM_ALO + o) = xl;
                float v = __bfloat162float(xh) + __bfloat162float(xl);
                s += v * v;
            }
            #pragma unroll
            for (int o = 16; o; o >>= 1) s += __shfl_xor_sync(0xFFFFFFFFu, s, o);
            if (l == 0) inv[row] = 1.0f / fmaxf(sqrtf(s), 1e-12f);
        }
    }
    __syncthreads();    // staging region dead; B tiles may now be written

    // ---- Phase 2: bilinear sampling, warp per (map,j) task, lane = 4 ch ----
    #pragma unroll
    for (int m = 0; m < 13; m++) {
        int task = w + 8 * m;                // 0..103
        if (task < 98) {
            int map = (task >= WIN2);
            int j   = task - WIN2 * map;
            const float* wp = wgt + task * 4;    // broadcast LDS
            const int*   ip = cidx + task * 4;
            float w0 = wp[0], w1 = wp[1], w2 = wp[2], w3 = wp[3];
            int   i0 = ip[0], i1 = ip[1], i2 = ip[2], i3 = ip[3];
            const float* F = map ? g_fmapT[1] : g_fmapT[0];
            int c4 = l * 4;
            float4 f0 = *(const float4*)(F + (size_t)i0 * CDIM + c4);
            float4 f1 = *(const float4*)(F + (size_t)i1 * CDIM + c4);
            float4 f2 = *(const float4*)(F + (size_t)i2 * CDIM + c4);
            float4 f3 = *(const float4*)(F + (size_t)i3 * CDIM + c4);
            float vx = w0 * f0.x + w1 * f1.x + w2 * f2.x + w3 * f3.x;
            float vy = w0 * f0.y + w1 * f1.y + w2 * f2.y + w3 * f3.y;
            float vz = w0 * f0.z + w1 * f1.z + w2 * f2.z + w3 * f3.z;
            float vw = w0 * f0.w + w1 * f1.w + w2 * f2.w + w3 * f3.w;

            __nv_bfloat16 h0 = __float2bfloat16(vx);
            __nv_bfloat16 h1 = __float2bfloat16(vy);
            __nv_bfloat16 h2 = __float2bfloat16(vz);
            __nv_bfloat16 h3 = __float2bfloat16(vw);
            __nv_bfloat16 e0 = __float2bfloat16(vx - __bfloat162float(h0));
            __nv_bfloat16 e1 = __float2bfloat16(vy - __bfloat162float(h1));
            __nv_bfloat16 e2 = __float2bfloat16(vz - __bfloat162float(h2));
            __nv_bfloat16 e3 = __float2bfloat16(vw - __bfloat162float(h3));

            uint2 hp, lp;
            hp.x = ((uint32_t)__bfloat16_as_ushort(h1) << 16) | __bfloat16_as_ushort(h0);
            hp.y = ((uint32_t)__bfloat16_as_ushort(h3) << 16) | __bfloat16_as_ushort(h2);
            lp.x = ((uint32_t)__bfloat16_as_ushort(e1) << 16) | __bfloat16_as_ushort(e0);
            lp.y = ((uint32_t)__bfloat16_as_ushort(e3) << 16) | __bfloat16_as_ushort(e2);

            int hbase = map ? SM_BHI : SM_AHI;
            int lbase = map ? SM_BLO : SM_ALO;
            uint32_t o = (uint32_t)(j * KS + c4) * 2u;       // 8B-aligned
            *(uint2*)(smc + hbase + o) = hp;
            *(uint2*)(smc + lbase + o) = lp;

            float r0f = __bfloat162float(h0) + __bfloat162float(e0);
            float r1f = __bfloat162float(h1) + __bfloat162float(e1);
            float r2f = __bfloat162float(h2) + __bfloat162float(e2);
            float r3f = __bfloat162float(h3) + __bfloat162float(e3);
            float s = r0f * r0f + r1f * r1f + r2f * r2f + r3f * r3f;
            #pragma unroll
            for (int o2 = 16; o2; o2 >>= 1) s += __shfl_xor_sync(0xFFFFFFFFu, s, o2);
            if (l == 0) inv[map ? (98 + j) : j] = 1.0f / fmaxf(sqrtf(s), 1e-12f);
        }
    }
    __syncthreads();

    // ---- Phase 3: HMMA correlations, warps 0-6, m-tile = 16w ----
    if (w < 7) {
        const int m0 = w * 16;
        const int lrow = l & 7, lq = l >> 3;
        uint32_t aoff = (uint32_t)((m0 + lrow + ((lq & 1) << 3)) * KS
                                   + ((lq >> 1) << 3)) * 2u;
        uint32_t aAhi = sbase + SM_AHI + aoff;
        uint32_t aAlo = sbase + SM_ALO + aoff;

        uint32_t ahi[8][4], alo[8][4];
        #pragma unroll
        for (int k8 = 0; k8 < 8; k8++) {
            ldsm4(ahi[k8], aAhi + 32u * k8);
            ldsm4(alo[k8], aAlo + 32u * k8);
        }

        const int li = l & 15;
        uint32_t boff = (uint32_t)(((li & 7) * KS) + ((li >> 3) << 3)) * 2u;

        const int r0 = m0 + (l >> 2);
        const int r1 = r0 + 8;
        const int kc = (l & 3) << 1;

        float ia0 = 0.f, ia1 = 0.f;
        int sel0 = 0, h0 = 0, sel1 = 0, h1 = 0;
        if (r0 < 98) { ia0 = inv[r0]; sel0 = (r0 >= 49); h0 = r0 - sel0 * 49; }
        if (r1 < 98) { ia1 = inv[r1]; sel1 = (r1 >= 49); h1 = r1 - sel1 * 49; }
        float* outp = out + (size_t)n * OUTP;

        #pragma unroll
        for (int nt = 0; nt < 7; nt++) {
            const int n0 = nt * 8;
            uint32_t bh_a = sbase + SM_BHI + boff + (uint32_t)(n0 * KS) * 2u;
            uint32_t bl_a = sbase + SM_BLO + boff + (uint32_t)(n0 * KS) * 2u;
            float acc[4] = {0.f, 0.f, 0.f, 0.f};
            #pragma unroll
            for (int k8 = 0; k8 < 8; k8++) {
                uint32_t bh[2], bl[2];
                ldsm2(bh, bh_a + 32u * k8);
                ldsm2(bl, bl_a + 32u * k8);
                mma16816(acc, ahi[k8], bh);
                mma16816(acc, ahi[k8], bl);
                mma16816(acc, alo[k8], bh);
            }
            const int k0 = n0 + kc;
            const int k1 = k0 + 1;
            float ib0 = inv[98 + k0];
            float ib1 = inv[98 + k1];
            if (r0 < 98) {
                float* op = outp + sel0 * (WIN2 * WIN2) + h0 * WIN2;
                if (k0 < WIN2) op[k0] = acc[0] * ia0 * ib0;
                if (k1 < WIN2) op[k1] = acc[1] * ia0 * ib1;
            }
            if (r1 < 98) {
                float* op = outp + sel1 * (WIN2 * WIN2) + h1 * WIN2;
                if (k0 < WIN2) op[k0] = acc[2] * ia1 * ib0;
                if (k1 < WIN2) op[k1] = acc[3] * ia1 * ib1;
            }
        }
    }
}

// ---------------------------------------------------------------------------
extern "C" void kernel_launch(void* const* d_in, const int* in_sizes, int n_in,
                              void* d_out, int out_size)
{
    const float* fmap_old = (const float*)d_in[0];
    const float* fmap_new = (const float*)d_in[1];
    const float* queries  = (const float*)d_in[2];
    const float* pred_pos = (const float*)d_in[3];
    const float* anchors  = (const float*)d_in[4];
    float* out = (float*)d_out;

    const int N = in_sizes[2] / 2;

    cudaFuncSetAttribute(glu_hmma_kernel,
                         cudaFuncAttributeMaxDynamicSharedMemorySize, SMEM_TOTAL);

    transpose_k<<<HWPX, CDIM>>>(fmap_old, fmap_new);
    glu_hmma_kernel<<<N, 256, SMEM_TOTAL>>>(queries, pred_pos, anchors, out);
}